// round 8
// baseline (speedup 1.0000x reference)
#include <cuda_runtime.h>
#include <cuda_bf16.h>
#include <math.h>
#include <stdint.h>

// Problem constants
#define NG    4096
#define KPOS  4
#define H     256
#define MNEG  64
#define NROWS (NG * KPOS)       // 16384 embedding rows
#define KDIM  768               // (KPOS-1)*H
#define LDAH  1024              // halves per emb row-group in g_Ebf (KPOS*H)
#define NLOG  65

#define ZSPLIT 4
#define KS    (KDIM / ZSPLIT)   // 192 k per z-block

// Scratch (static device arrays; allocation-free rule)
__device__ __align__(16) __nv_bfloat16 g_Ebf[NROWS * H];   // full emb, bf16 (8 MB)
__device__ __align__(16) __nv_bfloat16 g_WTbf[H * KDIM];   // W^T, bf16, [n][k]
__device__ float g_pred4[ZSPLIT * NG * H];                 // split-K partials
__device__ __align__(16) float g_terms[NG];
__device__ int   g_ctr = 0;                                // last-block counter

// ---------------------------------------------------------------------------
// Kernel 0: convert full emb -> bf16, W -> bf16 transposed.
// ---------------------------------------------------------------------------
#define EMB_PAIRS  (NROWS * H / 2)        // 2,097,152
#define EMB_BLOCKS (EMB_PAIRS / 256)      // 8192
#define WT_BLOCKS  (H * KDIM / 256)       // 768

__global__ __launch_bounds__(256) void convert_kernel(const float* __restrict__ emb,
                                                      const float* __restrict__ W) {
    int b = blockIdx.x;
    if (b < EMB_BLOCKS) {
        int idx = b * 256 + threadIdx.x;          // pair index
        float2 v = *(const float2*)(emb + 2 * (size_t)idx);
        *(__nv_bfloat162*)&g_Ebf[2 * (size_t)idx] = __floats2bfloat162_rn(v.x, v.y);
    } else {
        int t = (b - EMB_BLOCKS) * 256 + threadIdx.x;   // 0 .. H*KDIM-1
        int n = t / KDIM;
        int k = t % KDIM;
        g_WTbf[t] = __float2bfloat16_rn(W[(size_t)k * H + n]);  // coalesced write
    }
}

// ---------------------------------------------------------------------------
// Kernel A: predicts = hist_x @ W + b  via bf16 mma.m16n8k16, fp32 accum.
// A read from g_Ebf with lda=1024 halves (hist view = emb rows in place).
// BM=64 BN=64 BK=16, 128 threads = 4 warps (2x2), warp tile 32x32.
// Grid (4, 64, 4): z = split-K quarter (K=192 each) into g_pred4.
// ---------------------------------------------------------------------------
#define BKH 16                       // k halves per iteration
#define ITERS (KS / BKH)             // 12
#define STG 4
#define ROWH 24                      // padded halves per smem row (conflict-free)
#define A_ST_H (64 * ROWH)           // 1536 halves
#define STAGE_H (2 * A_ST_H)         // 3072 halves = 6144 B

__device__ __forceinline__ void cp16b(__nv_bfloat16* dst_smem, const __nv_bfloat16* src) {
    uint32_t d = (uint32_t)__cvta_generic_to_shared(dst_smem);
    asm volatile("cp.async.cg.shared.global [%0], [%1], 16;\n" :: "r"(d), "l"(src));
}

__global__ __launch_bounds__(128) void gemm_bf16(const float* __restrict__ bias) {
    __shared__ __align__(16) __nv_bfloat16 smem[STG * STAGE_H];

    const int tid  = threadIdx.x;
    const int warp = tid >> 5;
    const int lane = tid & 31;
    const int gid  = lane >> 2;          // mma groupID
    const int tq   = lane & 3;           // mma threadID-in-group
    const int wm0  = (warp >> 1) * 32;
    const int wn0  = (warp & 1) * 32;
    const int bm0  = blockIdx.y * 64;
    const int bn0  = blockIdx.x * 64;
    const int kz   = blockIdx.z * KS;

    const int crow = tid >> 1;           // 0..63
    const int koff = (tid & 1) * 8;      // halves

    const __nv_bfloat16* Asrc = g_Ebf  + (size_t)(bm0 + crow) * LDAH + kz + koff;
    const __nv_bfloat16* Bsrc = g_WTbf + (size_t)(bn0 + crow) * KDIM + kz + koff;

    float c[2][4][4];
#pragma unroll
    for (int i = 0; i < 2; i++)
#pragma unroll
        for (int j = 0; j < 4; j++)
#pragma unroll
            for (int q = 0; q < 4; q++) c[i][j][q] = 0.0f;

#pragma unroll
    for (int s = 0; s < STG - 1; s++) {
        __nv_bfloat16* st = smem + s * STAGE_H;
        cp16b(st + crow * ROWH + koff, Asrc + s * BKH);
        cp16b(st + A_ST_H + crow * ROWH + koff, Bsrc + s * BKH);
        asm volatile("cp.async.commit_group;\n" ::: "memory");
    }

#pragma unroll 4
    for (int it = 0; it < ITERS; it++) {
        asm volatile("cp.async.wait_group 2;\n" ::: "memory");
        __syncthreads();

        int nit = it + STG - 1;
        if (nit < ITERS) {
            __nv_bfloat16* st = smem + (nit % STG) * STAGE_H;
            cp16b(st + crow * ROWH + koff, Asrc + nit * BKH);
            cp16b(st + A_ST_H + crow * ROWH + koff, Bsrc + nit * BKH);
        }
        asm volatile("cp.async.commit_group;\n" ::: "memory");

        const __nv_bfloat16* As = smem + (it % STG) * STAGE_H;
        const __nv_bfloat16* Bs = As + A_ST_H;

        uint32_t a[2][4], b[4][2];
#pragma unroll
        for (int mf = 0; mf < 2; mf++) {
            int m = wm0 + mf * 16 + gid;
            a[mf][0] = *(const uint32_t*)&As[m * ROWH + 2 * tq];
            a[mf][1] = *(const uint32_t*)&As[(m + 8) * ROWH + 2 * tq];
            a[mf][2] = *(const uint32_t*)&As[m * ROWH + 2 * tq + 8];
            a[mf][3] = *(const uint32_t*)&As[(m + 8) * ROWH + 2 * tq + 8];
        }
#pragma unroll
        for (int nf = 0; nf < 4; nf++) {
            int n = wn0 + nf * 8 + gid;
            b[nf][0] = *(const uint32_t*)&Bs[n * ROWH + 2 * tq];
            b[nf][1] = *(const uint32_t*)&Bs[n * ROWH + 2 * tq + 8];
        }
#pragma unroll
        for (int mf = 0; mf < 2; mf++)
#pragma unroll
            for (int nf = 0; nf < 4; nf++) {
                asm volatile(
                    "mma.sync.aligned.m16n8k16.row.col.f32.bf16.bf16.f32 "
                    "{%0,%1,%2,%3}, {%4,%5,%6,%7}, {%8,%9}, {%0,%1,%2,%3};"
                    : "+f"(c[mf][nf][0]), "+f"(c[mf][nf][1]),
                      "+f"(c[mf][nf][2]), "+f"(c[mf][nf][3])
                    : "r"(a[mf][0]), "r"(a[mf][1]), "r"(a[mf][2]), "r"(a[mf][3]),
                      "r"(b[nf][0]), "r"(b[nf][1]));
            }
    }

    float* outb = g_pred4 + (size_t)blockIdx.z * NG * H;
#pragma unroll
    for (int mf = 0; mf < 2; mf++) {
        int m = bm0 + wm0 + mf * 16 + gid;
#pragma unroll
        for (int nf = 0; nf < 4; nf++) {
            int n = bn0 + wn0 + nf * 8 + 2 * tq;
            float bx = 0.0f, by = 0.0f;
            if (blockIdx.z == 0) {
                float2 bb = *(const float2*)(bias + n);
                bx = bb.x; by = bb.y;
            }
            *(float2*)&outb[(size_t)m * H + n] =
                make_float2(c[mf][nf][0] + bx, c[mf][nf][1] + by);
            *(float2*)&outb[(size_t)(m + 8) * H + n] =
                make_float2(c[mf][nf][2] + bx, c[mf][nf][3] + by);
        }
    }
}

// ---------------------------------------------------------------------------
// Kernel B: per-group logits + log-softmax term + fused last-block mean.
// bf16 gather (512 B/row, one uint4 per lane), fp32 dot with s_pred.
// Final block (detected via atomic counter) sums g_terms deterministically.
// ---------------------------------------------------------------------------
__global__ __launch_bounds__(256) void loss_kernel(const int* __restrict__ perm,
                                                   float* __restrict__ out) {
    const int g    = blockIdx.x;
    const int tid  = threadIdx.x;
    const int warp = tid >> 5;
    const int lane = tid & 31;

    __shared__ float s_pred[H];
    __shared__ float s_logits[NLOG];
    __shared__ int   s_row[NLOG];
    __shared__ int   s_last;

    {
        const float* pp = g_pred4 + (size_t)g * H + tid;
        s_pred[tid] = (pp[0] + pp[(size_t)NG * H])
                    + (pp[2 * (size_t)NG * H] + pp[3 * (size_t)NG * H]);
    }
    if (tid < MNEG) {
        int p = perm[(size_t)g * MNEG + tid];
        s_row[tid + 1] = p + ((p >= 4 * g) ? 4 : 0);
    }
    if (tid == MNEG) s_row[0] = 4 * g + 3;
    __syncthreads();

    // each lane owns 8 consecutive pred floats (halves 8*lane .. 8*lane+7)
    const float4* p4 = (const float4*)s_pred;
    const float4 pa = p4[2 * lane];
    const float4 pb = p4[2 * lane + 1];

    for (int j = warp; j < NLOG; j += 8) {
        const uint4* e = (const uint4*)(g_Ebf + (size_t)s_row[j] * H);
        uint4 v = e[lane];                       // 8 bf16 halves
        float2 f0 = __bfloat1622float2(*(const __nv_bfloat162*)&v.x);
        float2 f1 = __bfloat1622float2(*(const __nv_bfloat162*)&v.y);
        float2 f2 = __bfloat1622float2(*(const __nv_bfloat162*)&v.z);
        float2 f3 = __bfloat1622float2(*(const __nv_bfloat162*)&v.w);
        float s = f0.x * pa.x + f0.y * pa.y + f1.x * pa.z + f1.y * pa.w
                + f2.x * pb.x + f2.y * pb.y + f3.x * pb.z + f3.y * pb.w;
#pragma unroll
        for (int off = 16; off > 0; off >>= 1)
            s += __shfl_down_sync(0xffffffffu, s, off);
        if (lane == 0) s_logits[j] = s;
    }
    __syncthreads();

    if (warp == 0) {
        float v0 = s_logits[lane];
        float v1 = s_logits[lane + 32];
        float v2 = (lane == 0) ? s_logits[64] : -INFINITY;
        float m = fmaxf(fmaxf(v0, v1), v2);
#pragma unroll
        for (int off = 16; off > 0; off >>= 1)
            m = fmaxf(m, __shfl_xor_sync(0xffffffffu, m, off));
        float s = expf(v0 - m) + expf(v1 - m) + ((lane == 0) ? expf(v2 - m) : 0.0f);
#pragma unroll
        for (int off = 16; off > 0; off >>= 1)
            s += __shfl_xor_sync(0xffffffffu, s, off);
        float lse = m + logf(s);
        if (lane == 0) g_terms[g] = lse - s_logits[0];
    }

    // ---- fused deterministic mean: last block to finish does the sum ----
    if (tid == 0) {
        __threadfence();                         // publish g_terms[g]
        int c = atomicAdd(&g_ctr, 1);
        s_last = (c == NG - 1) ? 1 : 0;
    }
    __syncthreads();
    if (s_last) {
        __threadfence();                         // acquire all g_terms
        __shared__ float sr[256];
        const float4* p = (const float4*)g_terms;
        float4 a = p[4 * tid + 0];
        float4 b = p[4 * tid + 1];
        float4 cc = p[4 * tid + 2];
        float4 d = p[4 * tid + 3];
        float v = ((a.x + a.y) + (a.z + a.w)) + ((b.x + b.y) + (b.z + b.w))
                + ((cc.x + cc.y) + (cc.z + cc.w)) + ((d.x + d.y) + (d.z + d.w));
        sr[tid] = v;
        __syncthreads();
        for (int st = 128; st > 0; st >>= 1) {
            if (tid < st) sr[tid] += sr[tid + st];
            __syncthreads();
        }
        if (tid == 0) {
            out[0] = sr[0] / (float)NG;
            g_ctr = 0;                           // reset for next graph replay
        }
    }
}

// ---------------------------------------------------------------------------
extern "C" void kernel_launch(void* const* d_in, const int* in_sizes, int n_in,
                              void* d_out, int out_size) {
    const float* emb  = (const float*)d_in[0];   // (16384, 256) f32
    const float* W    = (const float*)d_in[1];   // (768, 256)   f32
    const float* bias = (const float*)d_in[2];   // (256,)       f32
    // d_in[3] = target (analytic, unused)
    const int* perm   = (const int*)d_in[4];     // (4096, 64)   int32

    convert_kernel<<<EMB_BLOCKS + WT_BLOCKS, 256>>>(emb, W);
    dim3 ggrid(H / 64, NG / 64, ZSPLIT);   // (4, 64, 4) = 1024 blocks
    gemm_bf16<<<ggrid, 128>>>(bias);
    loss_kernel<<<NG, 256>>>(perm, (float*)d_out);
}

// round 9
// speedup vs baseline: 1.1364x; 1.1364x over previous
#include <cuda_runtime.h>
#include <cuda_bf16.h>
#include <math.h>
#include <stdint.h>

// Problem constants
#define NG    4096
#define KPOS  4
#define H     256
#define MNEG  64
#define NROWS (NG * KPOS)       // 16384 embedding rows
#define KDIM  768               // (KPOS-1)*H
#define LDAH  1024              // halves per emb row-group in g_Ebf (KPOS*H)
#define NLOG  65

#define ZSPLIT 4
#define KS    (KDIM / ZSPLIT)   // 192 k per z-block

// Scratch (static device arrays; allocation-free rule)
__device__ __align__(16) __nv_bfloat16 g_Ebf[NROWS * H];   // full emb, bf16 (8 MB)
__device__ __align__(16) __nv_bfloat16 g_WTbf[H * KDIM];   // W^T, bf16, [n][k]
__device__ float g_pred4[ZSPLIT * NG * H];                 // split-K partials
__device__ __align__(16) float g_terms[NG];

// ---------------------------------------------------------------------------
// Kernel 0: convert. emb -> bf16 (8 floats/thread, vectorized);
// W -> bf16 transposed via 32x32 smem tile (both directions coalesced).
// ---------------------------------------------------------------------------
#define EMB_OCTS   (NROWS * H / 8)        // 524288 8-float units
#define EMB_BLOCKS (EMB_OCTS / 256)       // 2048
#define WT_TILES   ((KDIM / 32) * (H / 32))   // 24*8 = 192

__global__ __launch_bounds__(256) void convert_kernel(const float* __restrict__ emb,
                                                      const float* __restrict__ W) {
    int b = blockIdx.x;
    if (b < EMB_BLOCKS) {
        size_t idx = (size_t)(b * 256 + threadIdx.x) * 8;
        const float4* src = (const float4*)(emb + idx);
        float4 v0 = src[0];
        float4 v1 = src[1];
        uint4 o;
        *(__nv_bfloat162*)&o.x = __floats2bfloat162_rn(v0.x, v0.y);
        *(__nv_bfloat162*)&o.y = __floats2bfloat162_rn(v0.z, v0.w);
        *(__nv_bfloat162*)&o.z = __floats2bfloat162_rn(v1.x, v1.y);
        *(__nv_bfloat162*)&o.w = __floats2bfloat162_rn(v1.z, v1.w);
        *(uint4*)&g_Ebf[idx] = o;
    } else {
        // W^T tile transpose: tile (bk, bn) covers k0..k0+31, n0..n0+31
        __shared__ float tile[32][33];
        int b2 = b - EMB_BLOCKS;
        int n0 = (b2 & 7) * 32;
        int k0 = (b2 >> 3) * 32;
        int tx = threadIdx.x & 31;
        int ty = threadIdx.x >> 5;        // 0..7
#pragma unroll
        for (int i = 0; i < 4; i++) {
            int k = ty + 8 * i;
            tile[k][tx] = W[(size_t)(k0 + k) * H + n0 + tx];  // coalesced read
        }
        __syncthreads();
#pragma unroll
        for (int i = 0; i < 4; i++) {
            int n = ty + 8 * i;
            g_WTbf[(size_t)(n0 + n) * KDIM + k0 + tx] =
                __float2bfloat16_rn(tile[tx][n]);             // coalesced write
        }
    }
}

// ---------------------------------------------------------------------------
// Kernel A: predicts = hist_x @ W + b  via bf16 mma.m16n8k16, fp32 accum.
// A read from g_Ebf with lda=1024 halves (hist view = emb rows in place).
// BM=64 BN=64 BK=16, 128 threads = 4 warps (2x2), warp tile 32x32.
// Grid (4, 64, 4): z = split-K quarter (K=192 each) into g_pred4.
// ---------------------------------------------------------------------------
#define BKH 16                       // k halves per iteration
#define ITERS (KS / BKH)             // 12
#define STG 4
#define ROWH 24                      // padded halves per smem row (conflict-free)
#define A_ST_H (64 * ROWH)           // 1536 halves
#define STAGE_H (2 * A_ST_H)         // 3072 halves = 6144 B

__device__ __forceinline__ void cp16b(__nv_bfloat16* dst_smem, const __nv_bfloat16* src) {
    uint32_t d = (uint32_t)__cvta_generic_to_shared(dst_smem);
    asm volatile("cp.async.cg.shared.global [%0], [%1], 16;\n" :: "r"(d), "l"(src));
}

__global__ __launch_bounds__(128) void gemm_bf16(const float* __restrict__ bias) {
    __shared__ __align__(16) __nv_bfloat16 smem[STG * STAGE_H];

    const int tid  = threadIdx.x;
    const int warp = tid >> 5;
    const int lane = tid & 31;
    const int gid  = lane >> 2;          // mma groupID
    const int tq   = lane & 3;           // mma threadID-in-group
    const int wm0  = (warp >> 1) * 32;
    const int wn0  = (warp & 1) * 32;
    const int bm0  = blockIdx.y * 64;
    const int bn0  = blockIdx.x * 64;
    const int kz   = blockIdx.z * KS;

    const int crow = tid >> 1;           // 0..63
    const int koff = (tid & 1) * 8;      // halves

    const __nv_bfloat16* Asrc = g_Ebf  + (size_t)(bm0 + crow) * LDAH + kz + koff;
    const __nv_bfloat16* Bsrc = g_WTbf + (size_t)(bn0 + crow) * KDIM + kz + koff;

    float c[2][4][4];
#pragma unroll
    for (int i = 0; i < 2; i++)
#pragma unroll
        for (int j = 0; j < 4; j++)
#pragma unroll
            for (int q = 0; q < 4; q++) c[i][j][q] = 0.0f;

#pragma unroll
    for (int s = 0; s < STG - 1; s++) {
        __nv_bfloat16* st = smem + s * STAGE_H;
        cp16b(st + crow * ROWH + koff, Asrc + s * BKH);
        cp16b(st + A_ST_H + crow * ROWH + koff, Bsrc + s * BKH);
        asm volatile("cp.async.commit_group;\n" ::: "memory");
    }

#pragma unroll 4
    for (int it = 0; it < ITERS; it++) {
        asm volatile("cp.async.wait_group 2;\n" ::: "memory");
        __syncthreads();

        int nit = it + STG - 1;
        if (nit < ITERS) {
            __nv_bfloat16* st = smem + (nit % STG) * STAGE_H;
            cp16b(st + crow * ROWH + koff, Asrc + nit * BKH);
            cp16b(st + A_ST_H + crow * ROWH + koff, Bsrc + nit * BKH);
        }
        asm volatile("cp.async.commit_group;\n" ::: "memory");

        const __nv_bfloat16* As = smem + (it % STG) * STAGE_H;
        const __nv_bfloat16* Bs = As + A_ST_H;

        uint32_t a[2][4], b[4][2];
#pragma unroll
        for (int mf = 0; mf < 2; mf++) {
            int m = wm0 + mf * 16 + gid;
            a[mf][0] = *(const uint32_t*)&As[m * ROWH + 2 * tq];
            a[mf][1] = *(const uint32_t*)&As[(m + 8) * ROWH + 2 * tq];
            a[mf][2] = *(const uint32_t*)&As[m * ROWH + 2 * tq + 8];
            a[mf][3] = *(const uint32_t*)&As[(m + 8) * ROWH + 2 * tq + 8];
        }
#pragma unroll
        for (int nf = 0; nf < 4; nf++) {
            int n = wn0 + nf * 8 + gid;
            b[nf][0] = *(const uint32_t*)&Bs[n * ROWH + 2 * tq];
            b[nf][1] = *(const uint32_t*)&Bs[n * ROWH + 2 * tq + 8];
        }
#pragma unroll
        for (int mf = 0; mf < 2; mf++)
#pragma unroll
            for (int nf = 0; nf < 4; nf++) {
                asm volatile(
                    "mma.sync.aligned.m16n8k16.row.col.f32.bf16.bf16.f32 "
                    "{%0,%1,%2,%3}, {%4,%5,%6,%7}, {%8,%9}, {%0,%1,%2,%3};"
                    : "+f"(c[mf][nf][0]), "+f"(c[mf][nf][1]),
                      "+f"(c[mf][nf][2]), "+f"(c[mf][nf][3])
                    : "r"(a[mf][0]), "r"(a[mf][1]), "r"(a[mf][2]), "r"(a[mf][3]),
                      "r"(b[nf][0]), "r"(b[nf][1]));
            }
    }

    float* outb = g_pred4 + (size_t)blockIdx.z * NG * H;
#pragma unroll
    for (int mf = 0; mf < 2; mf++) {
        int m = bm0 + wm0 + mf * 16 + gid;
#pragma unroll
        for (int nf = 0; nf < 4; nf++) {
            int n = bn0 + wn0 + nf * 8 + 2 * tq;
            float bx = 0.0f, by = 0.0f;
            if (blockIdx.z == 0) {
                float2 bb = *(const float2*)(bias + n);
                bx = bb.x; by = bb.y;
            }
            *(float2*)&outb[(size_t)m * H + n] =
                make_float2(c[mf][nf][0] + bx, c[mf][nf][1] + by);
            *(float2*)&outb[(size_t)(m + 8) * H + n] =
                make_float2(c[mf][nf][2] + bx, c[mf][nf][3] + by);
        }
    }
}

// ---------------------------------------------------------------------------
// Kernel B: per-group logits + log-softmax term.
// bf16 gather (512 B/row, one uint4 per lane), fp32 dot with s_pred.
// ---------------------------------------------------------------------------
__global__ __launch_bounds__(256) void loss_kernel(const int* __restrict__ perm) {
    const int g    = blockIdx.x;
    const int tid  = threadIdx.x;
    const int warp = tid >> 5;
    const int lane = tid & 31;

    __shared__ float s_pred[H];
    __shared__ float s_logits[NLOG];
    __shared__ int   s_row[NLOG];

    {
        const float* pp = g_pred4 + (size_t)g * H + tid;
        s_pred[tid] = (pp[0] + pp[(size_t)NG * H])
                    + (pp[2 * (size_t)NG * H] + pp[3 * (size_t)NG * H]);
    }
    if (tid < MNEG) {
        int p = perm[(size_t)g * MNEG + tid];
        s_row[tid + 1] = p + ((p >= 4 * g) ? 4 : 0);
    }
    if (tid == MNEG) s_row[0] = 4 * g + 3;
    __syncthreads();

    // each lane owns 8 consecutive pred floats (halves 8*lane .. 8*lane+7)
    const float4* p4 = (const float4*)s_pred;
    const float4 pa = p4[2 * lane];
    const float4 pb = p4[2 * lane + 1];

    for (int j = warp; j < NLOG; j += 8) {
        const uint4* e = (const uint4*)(g_Ebf + (size_t)s_row[j] * H);
        uint4 v = e[lane];                       // 8 bf16 halves
        float2 f0 = __bfloat1622float2(*(const __nv_bfloat162*)&v.x);
        float2 f1 = __bfloat1622float2(*(const __nv_bfloat162*)&v.y);
        float2 f2 = __bfloat1622float2(*(const __nv_bfloat162*)&v.z);
        float2 f3 = __bfloat1622float2(*(const __nv_bfloat162*)&v.w);
        float s = f0.x * pa.x + f0.y * pa.y + f1.x * pa.z + f1.y * pa.w
                + f2.x * pb.x + f2.y * pb.y + f3.x * pb.z + f3.y * pb.w;
#pragma unroll
        for (int off = 16; off > 0; off >>= 1)
            s += __shfl_down_sync(0xffffffffu, s, off);
        if (lane == 0) s_logits[j] = s;
    }
    __syncthreads();

    if (warp == 0) {
        float v0 = s_logits[lane];
        float v1 = s_logits[lane + 32];
        float v2 = (lane == 0) ? s_logits[64] : -INFINITY;
        float m = fmaxf(fmaxf(v0, v1), v2);
#pragma unroll
        for (int off = 16; off > 0; off >>= 1)
            m = fmaxf(m, __shfl_xor_sync(0xffffffffu, m, off));
        float s = expf(v0 - m) + expf(v1 - m) + ((lane == 0) ? expf(v2 - m) : 0.0f);
#pragma unroll
        for (int off = 16; off > 0; off >>= 1)
            s += __shfl_xor_sync(0xffffffffu, s, off);
        float lse = m + logf(s);
        if (lane == 0) g_terms[g] = lse - s_logits[0];
    }
}

// ---------------------------------------------------------------------------
// Kernel C: deterministic mean. 512 thr, 8 contiguous floats each (2x float4).
// ---------------------------------------------------------------------------
__global__ __launch_bounds__(512) void reduce_kernel(float* __restrict__ out) {
    __shared__ float s[512];
    const int t = threadIdx.x;
    const float4* p = (const float4*)g_terms;
    float4 a = p[2 * t + 0];
    float4 b = p[2 * t + 1];
    float v = ((a.x + a.y) + (a.z + a.w)) + ((b.x + b.y) + (b.z + b.w));
    s[t] = v;
    __syncthreads();
    for (int st = 256; st > 0; st >>= 1) {
        if (t < st) s[t] += s[t + st];
        __syncthreads();
    }
    if (t == 0) out[0] = s[0] / (float)NG;
}

// ---------------------------------------------------------------------------
extern "C" void kernel_launch(void* const* d_in, const int* in_sizes, int n_in,
                              void* d_out, int out_size) {
    const float* emb  = (const float*)d_in[0];   // (16384, 256) f32
    const float* W    = (const float*)d_in[1];   // (768, 256)   f32
    const float* bias = (const float*)d_in[2];   // (256,)       f32
    // d_in[3] = target (analytic, unused)
    const int* perm   = (const int*)d_in[4];     // (4096, 64)   int32

    convert_kernel<<<EMB_BLOCKS + WT_TILES, 256>>>(emb, W);
    dim3 ggrid(H / 64, NG / 64, ZSPLIT);   // (4, 64, 4) = 1024 blocks
    gemm_bf16<<<ggrid, 128>>>(bias);
    loss_kernel<<<NG, 256>>>(perm);
    reduce_kernel<<<1, 512>>>((float*)d_out);
}

// round 10
// speedup vs baseline: 1.2500x; 1.1000x over previous
#include <cuda_runtime.h>
#include <cuda_bf16.h>
#include <math.h>
#include <stdint.h>

// Problem constants
#define NG    4096
#define KPOS  4
#define H     256
#define MNEG  64
#define NROWS (NG * KPOS)       // 16384 embedding rows
#define KDIM  768               // (KPOS-1)*H
#define LDAH  1024              // halves per emb row-group in g_Ebf (KPOS*H)
#define NLOG  65

#define ZSPLIT 4
#define KS    (KDIM / ZSPLIT)   // 192 k per z-block

// Scratch (static device arrays; allocation-free rule)
__device__ __align__(16) __nv_bfloat16 g_Ebf[NROWS * H];   // full emb, bf16 (8 MB)
__device__ __align__(16) __nv_bfloat16 g_WTbf[H * KDIM];   // W^T, bf16, [n][k]
__device__ float g_pred4[ZSPLIT * NG * H];                 // split-K partials

// ---------------------------------------------------------------------------
// Kernel 0: convert. emb -> bf16 (8 floats/thread, vectorized);
// W -> bf16 transposed via 32x32 smem tile. Block 0 also zeroes the output
// accumulator (graph-ordered before loss_kernel's atomic adds).
// ---------------------------------------------------------------------------
#define EMB_OCTS   (NROWS * H / 8)        // 524288 8-float units
#define EMB_BLOCKS (EMB_OCTS / 256)       // 2048
#define WT_TILES   ((KDIM / 32) * (H / 32))   // 24*8 = 192

__global__ __launch_bounds__(256) void convert_kernel(const float* __restrict__ emb,
                                                      const float* __restrict__ W,
                                                      float* __restrict__ out) {
    int b = blockIdx.x;
    if (b == 0 && threadIdx.x == 0) out[0] = 0.0f;   // reset accumulator
    if (b < EMB_BLOCKS) {
        size_t idx = (size_t)(b * 256 + threadIdx.x) * 8;
        const float4* src = (const float4*)(emb + idx);
        float4 v0 = src[0];
        float4 v1 = src[1];
        uint4 o;
        *(__nv_bfloat162*)&o.x = __floats2bfloat162_rn(v0.x, v0.y);
        *(__nv_bfloat162*)&o.y = __floats2bfloat162_rn(v0.z, v0.w);
        *(__nv_bfloat162*)&o.z = __floats2bfloat162_rn(v1.x, v1.y);
        *(__nv_bfloat162*)&o.w = __floats2bfloat162_rn(v1.z, v1.w);
        *(uint4*)&g_Ebf[idx] = o;
    } else {
        // W^T tile transpose: tile covers k0..k0+31, n0..n0+31
        __shared__ float tile[32][33];
        int b2 = b - EMB_BLOCKS;
        int n0 = (b2 & 7) * 32;
        int k0 = (b2 >> 3) * 32;
        int tx = threadIdx.x & 31;
        int ty = threadIdx.x >> 5;        // 0..7
#pragma unroll
        for (int i = 0; i < 4; i++) {
            int k = ty + 8 * i;
            tile[k][tx] = W[(size_t)(k0 + k) * H + n0 + tx];  // coalesced read
        }
        __syncthreads();
#pragma unroll
        for (int i = 0; i < 4; i++) {
            int n = ty + 8 * i;
            g_WTbf[(size_t)(n0 + n) * KDIM + k0 + tx] =
                __float2bfloat16_rn(tile[tx][n]);             // coalesced write
        }
    }
}

// ---------------------------------------------------------------------------
// Kernel A: predicts = hist_x @ W + b  via bf16 mma.m16n8k16, fp32 accum.
// BM=64 BN=64 BK=16, 128 threads = 4 warps (2x2), warp tile 32x32.
// Grid (4, 64, 4): z = split-K quarter (K=192 each) into g_pred4.
// ---------------------------------------------------------------------------
#define BKH 16                       // k halves per iteration
#define ITERS (KS / BKH)             // 12
#define STG 4
#define ROWH 24                      // padded halves per smem row (conflict-free)
#define A_ST_H (64 * ROWH)           // 1536 halves
#define STAGE_H (2 * A_ST_H)         // 3072 halves = 6144 B

__device__ __forceinline__ void cp16b(__nv_bfloat16* dst_smem, const __nv_bfloat16* src) {
    uint32_t d = (uint32_t)__cvta_generic_to_shared(dst_smem);
    asm volatile("cp.async.cg.shared.global [%0], [%1], 16;\n" :: "r"(d), "l"(src));
}

__global__ __launch_bounds__(128) void gemm_bf16(const float* __restrict__ bias) {
    __shared__ __align__(16) __nv_bfloat16 smem[STG * STAGE_H];

    const int tid  = threadIdx.x;
    const int warp = tid >> 5;
    const int lane = tid & 31;
    const int gid  = lane >> 2;          // mma groupID
    const int tq   = lane & 3;           // mma threadID-in-group
    const int wm0  = (warp >> 1) * 32;
    const int wn0  = (warp & 1) * 32;
    const int bm0  = blockIdx.y * 64;
    const int bn0  = blockIdx.x * 64;
    const int kz   = blockIdx.z * KS;

    const int crow = tid >> 1;           // 0..63
    const int koff = (tid & 1) * 8;      // halves

    const __nv_bfloat16* Asrc = g_Ebf  + (size_t)(bm0 + crow) * LDAH + kz + koff;
    const __nv_bfloat16* Bsrc = g_WTbf + (size_t)(bn0 + crow) * KDIM + kz + koff;

    float c[2][4][4];
#pragma unroll
    for (int i = 0; i < 2; i++)
#pragma unroll
        for (int j = 0; j < 4; j++)
#pragma unroll
            for (int q = 0; q < 4; q++) c[i][j][q] = 0.0f;

#pragma unroll
    for (int s = 0; s < STG - 1; s++) {
        __nv_bfloat16* st = smem + s * STAGE_H;
        cp16b(st + crow * ROWH + koff, Asrc + s * BKH);
        cp16b(st + A_ST_H + crow * ROWH + koff, Bsrc + s * BKH);
        asm volatile("cp.async.commit_group;\n" ::: "memory");
    }

#pragma unroll 4
    for (int it = 0; it < ITERS; it++) {
        asm volatile("cp.async.wait_group 2;\n" ::: "memory");
        __syncthreads();

        int nit = it + STG - 1;
        if (nit < ITERS) {
            __nv_bfloat16* st = smem + (nit % STG) * STAGE_H;
            cp16b(st + crow * ROWH + koff, Asrc + nit * BKH);
            cp16b(st + A_ST_H + crow * ROWH + koff, Bsrc + nit * BKH);
        }
        asm volatile("cp.async.commit_group;\n" ::: "memory");

        const __nv_bfloat16* As = smem + (it % STG) * STAGE_H;
        const __nv_bfloat16* Bs = As + A_ST_H;

        uint32_t a[2][4], b[4][2];
#pragma unroll
        for (int mf = 0; mf < 2; mf++) {
            int m = wm0 + mf * 16 + gid;
            a[mf][0] = *(const uint32_t*)&As[m * ROWH + 2 * tq];
            a[mf][1] = *(const uint32_t*)&As[(m + 8) * ROWH + 2 * tq];
            a[mf][2] = *(const uint32_t*)&As[m * ROWH + 2 * tq + 8];
            a[mf][3] = *(const uint32_t*)&As[(m + 8) * ROWH + 2 * tq + 8];
        }
#pragma unroll
        for (int nf = 0; nf < 4; nf++) {
            int n = wn0 + nf * 8 + gid;
            b[nf][0] = *(const uint32_t*)&Bs[n * ROWH + 2 * tq];
            b[nf][1] = *(const uint32_t*)&Bs[n * ROWH + 2 * tq + 8];
        }
#pragma unroll
        for (int mf = 0; mf < 2; mf++)
#pragma unroll
            for (int nf = 0; nf < 4; nf++) {
                asm volatile(
                    "mma.sync.aligned.m16n8k16.row.col.f32.bf16.bf16.f32 "
                    "{%0,%1,%2,%3}, {%4,%5,%6,%7}, {%8,%9}, {%0,%1,%2,%3};"
                    : "+f"(c[mf][nf][0]), "+f"(c[mf][nf][1]),
                      "+f"(c[mf][nf][2]), "+f"(c[mf][nf][3])
                    : "r"(a[mf][0]), "r"(a[mf][1]), "r"(a[mf][2]), "r"(a[mf][3]),
                      "r"(b[nf][0]), "r"(b[nf][1]));
            }
    }

    float* outb = g_pred4 + (size_t)blockIdx.z * NG * H;
#pragma unroll
    for (int mf = 0; mf < 2; mf++) {
        int m = bm0 + wm0 + mf * 16 + gid;
#pragma unroll
        for (int nf = 0; nf < 4; nf++) {
            int n = bn0 + wn0 + nf * 8 + 2 * tq;
            float bx = 0.0f, by = 0.0f;
            if (blockIdx.z == 0) {
                float2 bb = *(const float2*)(bias + n);
                bx = bb.x; by = bb.y;
            }
            *(float2*)&outb[(size_t)m * H + n] =
                make_float2(c[mf][nf][0] + bx, c[mf][nf][1] + by);
            *(float2*)&outb[(size_t)(m + 8) * H + n] =
                make_float2(c[mf][nf][2] + bx, c[mf][nf][3] + by);
        }
    }
}

// ---------------------------------------------------------------------------
// Kernel B: per-group logits + log-softmax term, accumulated into out[0]
// via one atomicAdd per block. Gather loop unrolled x2 for MLP.
// ---------------------------------------------------------------------------
__global__ __launch_bounds__(256) void loss_kernel(const int* __restrict__ perm,
                                                   float* __restrict__ out) {
    const int g    = blockIdx.x;
    const int tid  = threadIdx.x;
    const int warp = tid >> 5;
    const int lane = tid & 31;

    __shared__ float s_pred[H];
    __shared__ float s_logits[NLOG];
    __shared__ int   s_row[NLOG];

    {
        const float* pp = g_pred4 + (size_t)g * H + tid;
        s_pred[tid] = (pp[0] + pp[(size_t)NG * H])
                    + (pp[2 * (size_t)NG * H] + pp[3 * (size_t)NG * H]);
    }
    if (tid < MNEG) {
        int p = perm[(size_t)g * MNEG + tid];
        s_row[tid + 1] = p + ((p >= 4 * g) ? 4 : 0);
    }
    if (tid == MNEG) s_row[0] = 4 * g + 3;
    __syncthreads();

    // each lane owns 8 consecutive pred floats (halves 8*lane .. 8*lane+7)
    const float4* p4 = (const float4*)s_pred;
    const float4 pa = p4[2 * lane];
    const float4 pb = p4[2 * lane + 1];

    // x2 unrolled gather: rows j and j+8 in flight together
    for (int j = warp; j < NLOG; j += 16) {
        uint4 v0 = ((const uint4*)(g_Ebf + (size_t)s_row[j] * H))[lane];
        bool has2 = (j + 8) < NLOG;
        uint4 v1 = has2 ? ((const uint4*)(g_Ebf + (size_t)s_row[j + 8] * H))[lane]
                        : make_uint4(0, 0, 0, 0);
        {
            float2 f0 = __bfloat1622float2(*(const __nv_bfloat162*)&v0.x);
            float2 f1 = __bfloat1622float2(*(const __nv_bfloat162*)&v0.y);
            float2 f2 = __bfloat1622float2(*(const __nv_bfloat162*)&v0.z);
            float2 f3 = __bfloat1622float2(*(const __nv_bfloat162*)&v0.w);
            float s = f0.x * pa.x + f0.y * pa.y + f1.x * pa.z + f1.y * pa.w
                    + f2.x * pb.x + f2.y * pb.y + f3.x * pb.z + f3.y * pb.w;
#pragma unroll
            for (int off = 16; off > 0; off >>= 1)
                s += __shfl_down_sync(0xffffffffu, s, off);
            if (lane == 0) s_logits[j] = s;
        }
        if (has2) {
            float2 f0 = __bfloat1622float2(*(const __nv_bfloat162*)&v1.x);
            float2 f1 = __bfloat1622float2(*(const __nv_bfloat162*)&v1.y);
            float2 f2 = __bfloat1622float2(*(const __nv_bfloat162*)&v1.z);
            float2 f3 = __bfloat1622float2(*(const __nv_bfloat162*)&v1.w);
            float s = f0.x * pa.x + f0.y * pa.y + f1.x * pa.z + f1.y * pa.w
                    + f2.x * pb.x + f2.y * pb.y + f3.x * pb.z + f3.y * pb.w;
#pragma unroll
            for (int off = 16; off > 0; off >>= 1)
                s += __shfl_down_sync(0xffffffffu, s, off);
            if (lane == 0) s_logits[j + 8] = s;
        }
    }
    __syncthreads();

    if (warp == 0) {
        float v0 = s_logits[lane];
        float v1 = s_logits[lane + 32];
        float v2 = (lane == 0) ? s_logits[64] : -INFINITY;
        float m = fmaxf(fmaxf(v0, v1), v2);
#pragma unroll
        for (int off = 16; off > 0; off >>= 1)
            m = fmaxf(m, __shfl_xor_sync(0xffffffffu, m, off));
        float s = expf(v0 - m) + expf(v1 - m) + ((lane == 0) ? expf(v2 - m) : 0.0f);
#pragma unroll
        for (int off = 16; off > 0; off >>= 1)
            s += __shfl_xor_sync(0xffffffffu, s, off);
        float lse = m + logf(s);
        if (lane == 0)
            atomicAdd(out, (lse - s_logits[0]) * (1.0f / (float)NG));
    }
}

// ---------------------------------------------------------------------------
extern "C" void kernel_launch(void* const* d_in, const int* in_sizes, int n_in,
                              void* d_out, int out_size) {
    const float* emb  = (const float*)d_in[0];   // (16384, 256) f32
    const float* W    = (const float*)d_in[1];   // (768, 256)   f32
    const float* bias = (const float*)d_in[2];   // (256,)       f32
    // d_in[3] = target (analytic, unused)
    const int* perm   = (const int*)d_in[4];     // (4096, 64)   int32

    convert_kernel<<<EMB_BLOCKS + WT_TILES, 256>>>(emb, W, (float*)d_out);
    dim3 ggrid(H / 64, NG / 64, ZSPLIT);   // (4, 64, 4) = 1024 blocks
    gemm_bf16<<<ggrid, 128>>>(bias);
    loss_kernel<<<NG, 256>>>(perm, (float*)d_out);
}